// round 1
// baseline (speedup 1.0000x reference)
#include <cuda_runtime.h>
#include <math.h>

#define NTOK 2048
#define BATCH 2
#define DIMV 768
#define NHEAD 12
#define HDIM 64
#define KNN 32
#define DFF 3072
#define MROWS 4096   // BATCH*NTOK

// scratch layout (floats):
// h[0], q[1], k[2], v[3], att[4], x2[5], h2[6] each MROWS*DIMV, ffn = MROWS*DFF
__device__ float g_scratch[7 * MROWS * DIMV + MROWS * DFF];
__device__ int   g_idx[MROWS * KNN];
__device__ float g_dist[MROWS * KNN];

// ---------------------------------------------------------------------------
// block reduce (256 threads = 8 warps)
// ---------------------------------------------------------------------------
__device__ __forceinline__ float block_reduce_sum(float v, float* sbuf) {
    __syncthreads();
    int lane = threadIdx.x & 31, w = threadIdx.x >> 5;
#pragma unroll
    for (int o = 16; o; o >>= 1) v += __shfl_xor_sync(0xffffffffu, v, o);
    if (lane == 0) sbuf[w] = v;
    __syncthreads();
    float r = (lane < 8) ? sbuf[lane] : 0.f;
#pragma unroll
    for (int o = 4; o; o >>= 1) r += __shfl_xor_sync(0xffffffffu, r, o);
    return __shfl_sync(0xffffffffu, r, 0);
}

// ---------------------------------------------------------------------------
// LayerNorm (+ optional time embedding)
// ---------------------------------------------------------------------------
__global__ void __launch_bounds__(256) ln_kernel(const float* __restrict__ x,
    const float* __restrict__ g, const float* __restrict__ be,
    const float* __restrict__ temb, float* __restrict__ out)
{
    __shared__ float sbuf[8];
    int row = blockIdx.x;
    const float* xr = x + (size_t)row * DIMV;
    float xl[3];
    float s = 0.f;
#pragma unroll
    for (int it = 0; it < 3; it++) { xl[it] = xr[threadIdx.x + it * 256]; s += xl[it]; }
    s = block_reduce_sum(s, sbuf);
    float mu = s * (1.0f / DIMV);
    float vs = 0.f;
#pragma unroll
    for (int it = 0; it < 3; it++) { float d = xl[it] - mu; vs += d * d; }
    vs = block_reduce_sum(vs, sbuf);
    float inv = rsqrtf(vs * (1.0f / DIMV) + 1e-5f);
    int b = row >> 11;
#pragma unroll
    for (int it = 0; it < 3; it++) {
        int i = threadIdx.x + it * 256;
        float o = (xl[it] - mu) * inv * g[i] + be[i];
        if (temb) o += temb[b * DIMV + i];
        out[(size_t)row * DIMV + i] = o;
    }
}

// ---------------------------------------------------------------------------
// SGEMM: C[M,Nc] = A[M,K] @ W[K,Nc] + bias (+gelu) (+residual)
// 128x128 tile, BK=8, 256 threads, 8x8 per-thread
// Requires M%128==0, Nc%128==0, K%8==0 (all true here)
// ---------------------------------------------------------------------------
__global__ void __launch_bounds__(256) sgemm_kernel(const float* __restrict__ A,
    const float* __restrict__ W, const float* __restrict__ bias,
    const float* __restrict__ res, float* __restrict__ C,
    int M, int Nc, int K, int act)
{
    __shared__ float As[8][128];
    __shared__ float Bs[8][128];
    int bm = blockIdx.y * 128, bn = blockIdx.x * 128;
    int tid = threadIdx.x;
    int tx = tid & 15, ty = tid >> 4;
    int arow = tid >> 1, acol = (tid & 1) * 4;
    int brow = tid >> 5, bcol = (tid & 31) * 4;
    const float* Aptr = A + (size_t)(bm + arow) * K + acol;
    const float* Wptr = W + (size_t)brow * Nc + bn + bcol;

    float acc[8][8];
#pragma unroll
    for (int i = 0; i < 8; i++)
#pragma unroll
        for (int j = 0; j < 8; j++) acc[i][j] = 0.f;

    for (int k0 = 0; k0 < K; k0 += 8) {
        float4 a = *(const float4*)(Aptr + k0);
        As[acol + 0][arow] = a.x; As[acol + 1][arow] = a.y;
        As[acol + 2][arow] = a.z; As[acol + 3][arow] = a.w;
        float4 bq4 = *(const float4*)(Wptr + (size_t)k0 * Nc);
        *(float4*)&Bs[brow][bcol] = bq4;
        __syncthreads();
#pragma unroll
        for (int kk = 0; kk < 8; kk++) {
            float ra[8], rb[8];
            *(float4*)&ra[0] = *(float4*)&As[kk][ty * 8];
            *(float4*)&ra[4] = *(float4*)&As[kk][ty * 8 + 4];
            *(float4*)&rb[0] = *(float4*)&Bs[kk][tx * 8];
            *(float4*)&rb[4] = *(float4*)&Bs[kk][tx * 8 + 4];
#pragma unroll
            for (int i = 0; i < 8; i++)
#pragma unroll
                for (int j = 0; j < 8; j++)
                    acc[i][j] = fmaf(ra[i], rb[j], acc[i][j]);
        }
        __syncthreads();
    }

#pragma unroll
    for (int i = 0; i < 8; i++) {
        int r = bm + ty * 8 + i;
#pragma unroll
        for (int j = 0; j < 8; j += 4) {
            int cidx = bn + tx * 8 + j;
            float4 o;
            o.x = acc[i][j + 0] + bias[cidx + 0];
            o.y = acc[i][j + 1] + bias[cidx + 1];
            o.z = acc[i][j + 2] + bias[cidx + 2];
            o.w = acc[i][j + 3] + bias[cidx + 3];
            if (act) {
                o.x = 0.5f * o.x * (1.f + erff(o.x * 0.70710678118654752f));
                o.y = 0.5f * o.y * (1.f + erff(o.y * 0.70710678118654752f));
                o.z = 0.5f * o.z * (1.f + erff(o.z * 0.70710678118654752f));
                o.w = 0.5f * o.w * (1.f + erff(o.w * 0.70710678118654752f));
            }
            if (res) {
                float4 rr = *(const float4*)(res + (size_t)r * Nc + cidx);
                o.x += rr.x; o.y += rr.y; o.z += rr.z; o.w += rr.w;
            }
            *(float4*)(C + (size_t)r * Nc + cidx) = o;
        }
    }
}

// ---------------------------------------------------------------------------
// Poincare distance + top-KNN (smallest) per row.
// One block per (b, i) row; arg = 1 + 2c|x-y|^2/((1-c|x|^2)(1-c|y|^2)+eps),
// ranking by arg == ranking by dist (arccosh monotone). Ties -> lower index.
// ---------------------------------------------------------------------------
__global__ void __launch_bounds__(256) topk_kernel(const float* __restrict__ pos,
    const float* __restrict__ cptr, int* __restrict__ idxo, float* __restrict__ disto)
{
    __shared__ float arg[NTOK];
    __shared__ float rv[8];
    __shared__ int ri[8];
    int row = blockIdx.x;
    int b = row >> 11, i = row & (NTOK - 1);
    float c = cptr[0];
    float inv_sqc = rsqrtf(c);
    const float* pb = pos + (size_t)b * NTOK * 2;
    float yx = pb[i * 2], yy = pb[i * 2 + 1];
    float denY = 1.f - c * (yx * yx + yy * yy);
    for (int j = threadIdx.x; j < NTOK; j += 256) {
        float xx = pb[j * 2], xy = pb[j * 2 + 1];
        float dx = xx - yx, dy = xy - yy;
        float num = 2.f * c * (dx * dx + dy * dy);
        float den = (1.f - c * (xx * xx + xy * xy)) * denY;
        arg[j] = fmaxf(1.f + num / (den + 1e-8f), 1.f);
    }
    __syncthreads();
    int lane = threadIdx.x & 31, w = threadIdx.x >> 5;
    for (int sel = 0; sel < KNN; sel++) {
        float bv = 3.4e38f; int bi = 0x7fffffff;
        for (int j = threadIdx.x; j < NTOK; j += 256) {
            float a = arg[j];
            if (a < bv) { bv = a; bi = j; }   // ascending j scan keeps lowest idx on ties
        }
#pragma unroll
        for (int o = 16; o; o >>= 1) {
            float ov = __shfl_xor_sync(0xffffffffu, bv, o);
            int   oi = __shfl_xor_sync(0xffffffffu, bi, o);
            if (ov < bv || (ov == bv && oi < bi)) { bv = ov; bi = oi; }
        }
        if (lane == 0) { rv[w] = bv; ri[w] = bi; }
        __syncthreads();
        if (threadIdx.x == 0) {
            float fv = rv[0]; int fi = ri[0];
            for (int t = 1; t < 8; t++)
                if (rv[t] < fv || (rv[t] == fv && ri[t] < fi)) { fv = rv[t]; fi = ri[t]; }
            idxo[(size_t)row * KNN + sel] = fi;
            disto[(size_t)row * KNN + sel] = acoshf(fv) * inv_sqc;
            arg[fi] = 3.4e38f;
        }
        __syncthreads();
    }
}

// ---------------------------------------------------------------------------
// kNN attention. One block per (b,n); warp = head; lane = neighbor for softmax.
// ---------------------------------------------------------------------------
__global__ void __launch_bounds__(384) attn_kernel(const float* __restrict__ q,
    const float* __restrict__ k, const float* __restrict__ v,
    const int* __restrict__ idx, const float* __restrict__ dist,
    const float* __restrict__ log_tau, float* __restrict__ out)
{
    __shared__ int sidx[KNN];
    __shared__ float sgeo[KNN];
    int row = blockIdx.x;
    int lane = threadIdx.x & 31, h = threadIdx.x >> 5;
    float invtau = 1.f / (expf(log_tau[0]) + 1e-8f);
    if (threadIdx.x < KNN) {
        sidx[threadIdx.x] = idx[(size_t)row * KNN + threadIdx.x];
        sgeo[threadIdx.x] = -dist[(size_t)row * KNN + threadIdx.x] * invtau;
    }
    __syncthreads();
    int b = row >> 11;
    const float* qp = q + (size_t)row * DIMV + h * HDIM;
    float q0 = qp[2 * lane], q1 = qp[2 * lane + 1];
    const float* kb = k + (size_t)b * NTOK * DIMV + h * HDIM;
    const float* vb = v + (size_t)b * NTOK * DIMV + h * HDIM;
    float myscore = 0.f;
#pragma unroll 4
    for (int j = 0; j < KNN; j++) {
        const float* kp = kb + (size_t)sidx[j] * DIMV;
        float p = q0 * kp[2 * lane] + q1 * kp[2 * lane + 1];
#pragma unroll
        for (int o = 16; o; o >>= 1) p += __shfl_xor_sync(0xffffffffu, p, o);
        if (lane == j) myscore = p * 0.125f + sgeo[j];
    }
    float m = myscore;
#pragma unroll
    for (int o = 16; o; o >>= 1) m = fmaxf(m, __shfl_xor_sync(0xffffffffu, m, o));
    float e = expf(myscore - m);
    float s = e;
#pragma unroll
    for (int o = 16; o; o >>= 1) s += __shfl_xor_sync(0xffffffffu, s, o);
    float p = e / s;
    float o0 = 0.f, o1 = 0.f;
#pragma unroll 4
    for (int j = 0; j < KNN; j++) {
        float pj = __shfl_sync(0xffffffffu, p, j);
        const float* vp = vb + (size_t)sidx[j] * DIMV;
        o0 += pj * vp[2 * lane]; o1 += pj * vp[2 * lane + 1];
    }
    float* op = out + (size_t)row * DIMV + h * HDIM;
    op[2 * lane] = o0; op[2 * lane + 1] = o1;
}

// ---------------------------------------------------------------------------
extern "C" void kernel_launch(void* const* d_in, const int* in_sizes, int n_in,
                              void* d_out, int out_size)
{
    const float* x    = (const float*)d_in[0];
    const float* pos  = (const float*)d_in[1];
    const float* c    = (const float*)d_in[2];
    const float* temb = (const float*)d_in[3];
    const float* Wq = (const float*)d_in[4],  *bq = (const float*)d_in[5];
    const float* Wk = (const float*)d_in[6],  *bk = (const float*)d_in[7];
    const float* Wv = (const float*)d_in[8],  *bv = (const float*)d_in[9];
    const float* Wo = (const float*)d_in[10], *bo = (const float*)d_in[11];
    const float* W1 = (const float*)d_in[12], *b1 = (const float*)d_in[13];
    const float* W2 = (const float*)d_in[14], *b2 = (const float*)d_in[15];
    const float* g1 = (const float*)d_in[16], *be1 = (const float*)d_in[17];
    const float* g2 = (const float*)d_in[18], *be2 = (const float*)d_in[19];
    const float* log_tau = (const float*)d_in[20];
    float* out = (float*)d_out;

    float* base; cudaGetSymbolAddress((void**)&base, g_scratch);
    int* idxp;   cudaGetSymbolAddress((void**)&idxp, g_idx);
    float* distp;cudaGetSymbolAddress((void**)&distp, g_dist);

    float* h   = base;
    float* q   = base + 1 * (size_t)MROWS * DIMV;
    float* k   = base + 2 * (size_t)MROWS * DIMV;
    float* v   = base + 3 * (size_t)MROWS * DIMV;
    float* att = base + 4 * (size_t)MROWS * DIMV;
    float* x2  = base + 5 * (size_t)MROWS * DIMV;
    float* h2  = base + 6 * (size_t)MROWS * DIMV;
    float* ffn = base + 7 * (size_t)MROWS * DIMV;

    ln_kernel<<<MROWS, 256>>>(x, g1, be1, temb, h);

    dim3 g768(DIMV / 128, MROWS / 128);
    sgemm_kernel<<<g768, 256>>>(h, Wq, bq, nullptr, q, MROWS, DIMV, DIMV, 0);
    sgemm_kernel<<<g768, 256>>>(h, Wk, bk, nullptr, k, MROWS, DIMV, DIMV, 0);
    sgemm_kernel<<<g768, 256>>>(h, Wv, bv, nullptr, v, MROWS, DIMV, DIMV, 0);

    topk_kernel<<<MROWS, 256>>>(pos, c, idxp, distp);
    attn_kernel<<<MROWS, 384>>>(q, k, v, idxp, distp, log_tau, att);

    sgemm_kernel<<<g768, 256>>>(att, Wo, bo, x, x2, MROWS, DIMV, DIMV, 0);
    ln_kernel<<<MROWS, 256>>>(x2, g2, be2, nullptr, h2);

    dim3 gff(DFF / 128, MROWS / 128);
    sgemm_kernel<<<gff, 256>>>(h2, W1, b1, nullptr, ffn, MROWS, DFF, DIMV, 1);
    sgemm_kernel<<<g768, 256>>>(ffn, W2, b2, x2, out, MROWS, DIMV, DFF, 0);
}

// round 2
// speedup vs baseline: 1.0505x; 1.0505x over previous
#include <cuda_runtime.h>
#include <math.h>

#define NTOK 2048
#define BATCH 2
#define DIMV 768
#define NHEAD 12
#define HDIM 64
#define KNN 32
#define DFF 3072
#define MROWS 4096   // BATCH*NTOK

__device__ float g_scratch[7 * MROWS * DIMV + MROWS * DFF];
__device__ int   g_idx[MROWS * KNN];
__device__ float g_dist[MROWS * KNN];

// ---------------------------------------------------------------------------
__device__ __forceinline__ float block_reduce_sum(float v, float* sbuf) {
    __syncthreads();
    int lane = threadIdx.x & 31, w = threadIdx.x >> 5;
#pragma unroll
    for (int o = 16; o; o >>= 1) v += __shfl_xor_sync(0xffffffffu, v, o);
    if (lane == 0) sbuf[w] = v;
    __syncthreads();
    float r = (lane < 8) ? sbuf[lane] : 0.f;
#pragma unroll
    for (int o = 4; o; o >>= 1) r += __shfl_xor_sync(0xffffffffu, r, o);
    return __shfl_sync(0xffffffffu, r, 0);
}

// ---------------------------------------------------------------------------
__global__ void __launch_bounds__(256) ln_kernel(const float* __restrict__ x,
    const float* __restrict__ g, const float* __restrict__ be,
    const float* __restrict__ temb, float* __restrict__ out)
{
    __shared__ float sbuf[8];
    int row = blockIdx.x;
    const float* xr = x + (size_t)row * DIMV;
    float xl[3];
    float s = 0.f;
#pragma unroll
    for (int it = 0; it < 3; it++) { xl[it] = xr[threadIdx.x + it * 256]; s += xl[it]; }
    s = block_reduce_sum(s, sbuf);
    float mu = s * (1.0f / DIMV);
    float vs = 0.f;
#pragma unroll
    for (int it = 0; it < 3; it++) { float d = xl[it] - mu; vs += d * d; }
    vs = block_reduce_sum(vs, sbuf);
    float inv = rsqrtf(vs * (1.0f / DIMV) + 1e-5f);
    int b = row >> 11;
#pragma unroll
    for (int it = 0; it < 3; it++) {
        int i = threadIdx.x + it * 256;
        float o = (xl[it] - mu) * inv * g[i] + be[i];
        if (temb) o += temb[b * DIMV + i];
        out[(size_t)row * DIMV + i] = o;
    }
}

// ---------------------------------------------------------------------------
// TF32 tensor-core GEMM with hi/lo error compensation.
// C[M,Nc] = A[M,K] @ W[K,Nc] + bias (+gelu) (+res). 128x128x16 tile,
// 256 threads = 8 warps, warp tile 64x32 via m16n8k8 mma (4x4 tiles).
// SMEM stride 136 -> conflict-free fragment loads (bank = 8*t + g).
// ---------------------------------------------------------------------------
__device__ __forceinline__ float tf32_rna(float x) {
    unsigned u;
    asm("cvt.rna.tf32.f32 %0, %1;" : "=r"(u) : "f"(x));
    return __uint_as_float(u);
}

#define MMA_TF32(d, a0, a1, a2, a3, b0, b1)                                   \
    asm volatile(                                                             \
        "mma.sync.aligned.m16n8k8.row.col.f32.tf32.tf32.f32 "                 \
        "{%0,%1,%2,%3},{%4,%5,%6,%7},{%8,%9},{%0,%1,%2,%3};"                  \
        : "+f"(d[0]), "+f"(d[1]), "+f"(d[2]), "+f"(d[3])                      \
        : "r"(__float_as_uint(a0)), "r"(__float_as_uint(a1)),                 \
          "r"(__float_as_uint(a2)), "r"(__float_as_uint(a3)),                 \
          "r"(__float_as_uint(b0)), "r"(__float_as_uint(b1)))

#define SMS 136   // smem row stride (floats)

__global__ void __launch_bounds__(256, 1) mma_gemm_kernel(
    const float* __restrict__ A, const float* __restrict__ W,
    const float* __restrict__ bias, const float* __restrict__ res,
    float* __restrict__ C, int M, int Nc, int K, int act)
{
    __shared__ float Ahi[16 * SMS], Alo[16 * SMS];
    __shared__ float Bhi[16 * SMS], Blo[16 * SMS];

    const int tid = threadIdx.x;
    const int warp = tid >> 5, lane = tid & 31;
    const int g = lane >> 2, t = lane & 3;
    const int wm = warp & 1, wn = warp >> 1;
    const int bm = blockIdx.y * 128, bn = blockIdx.x * 128;

    // GMEM staging assignment
    const int a_kv = tid >> 6;          // 0..3 (float4 along k)
    const int a_m  = tid & 63;          // rows a_m, a_m+64
    const int b_k  = tid >> 5;          // 0..7 (rows b_k, b_k+8)
    const int b_nv = tid & 31;          // float4 along n

    const float* Ap = A + (size_t)(bm + a_m) * K + a_kv * 4;
    const float* Wp = W + (size_t)b_k * Nc + bn + b_nv * 4;

    float4 ra0, ra1, rb0, rb1;
    ra0 = *(const float4*)(Ap);
    ra1 = *(const float4*)(Ap + (size_t)64 * K);
    rb0 = *(const float4*)(Wp);
    rb1 = *(const float4*)(Wp + (size_t)8 * Nc);

    float acc[4][4][4];
#pragma unroll
    for (int mi = 0; mi < 4; mi++)
#pragma unroll
        for (int ni = 0; ni < 4; ni++)
#pragma unroll
            for (int e = 0; e < 4; e++) acc[mi][ni][e] = 0.f;

    const int arow = wm * 64 + g;
    const int bcol = wn * 32 + g;

    for (int k0 = 0; k0 < K; k0 += 16) {
        __syncthreads();
        // store + hi/lo split
        {
            const float* av = (const float*)&ra0;
#pragma unroll
            for (int e = 0; e < 4; e++) {
                float hi = tf32_rna(av[e]);
                Ahi[(a_kv * 4 + e) * SMS + a_m] = hi;
                Alo[(a_kv * 4 + e) * SMS + a_m] = tf32_rna(av[e] - hi);
            }
            av = (const float*)&ra1;
#pragma unroll
            for (int e = 0; e < 4; e++) {
                float hi = tf32_rna(av[e]);
                Ahi[(a_kv * 4 + e) * SMS + a_m + 64] = hi;
                Alo[(a_kv * 4 + e) * SMS + a_m + 64] = tf32_rna(av[e] - hi);
            }
            float4 h4, l4;
            h4.x = tf32_rna(rb0.x); l4.x = tf32_rna(rb0.x - h4.x);
            h4.y = tf32_rna(rb0.y); l4.y = tf32_rna(rb0.y - h4.y);
            h4.z = tf32_rna(rb0.z); l4.z = tf32_rna(rb0.z - h4.z);
            h4.w = tf32_rna(rb0.w); l4.w = tf32_rna(rb0.w - h4.w);
            *(float4*)&Bhi[b_k * SMS + b_nv * 4] = h4;
            *(float4*)&Blo[b_k * SMS + b_nv * 4] = l4;
            h4.x = tf32_rna(rb1.x); l4.x = tf32_rna(rb1.x - h4.x);
            h4.y = tf32_rna(rb1.y); l4.y = tf32_rna(rb1.y - h4.y);
            h4.z = tf32_rna(rb1.z); l4.z = tf32_rna(rb1.z - h4.z);
            h4.w = tf32_rna(rb1.w); l4.w = tf32_rna(rb1.w - h4.w);
            *(float4*)&Bhi[(b_k + 8) * SMS + b_nv * 4] = h4;
            *(float4*)&Blo[(b_k + 8) * SMS + b_nv * 4] = l4;
        }
        __syncthreads();

        // prefetch next tile
        if (k0 + 16 < K) {
            ra0 = *(const float4*)(Ap + k0 + 16);
            ra1 = *(const float4*)(Ap + (size_t)64 * K + k0 + 16);
            rb0 = *(const float4*)(Wp + (size_t)(k0 + 16) * Nc);
            rb1 = *(const float4*)(Wp + (size_t)(k0 + 24) * Nc);
        }

#pragma unroll
        for (int kk = 0; kk < 16; kk += 8) {
            const int r0 = (kk + t) * SMS, r1 = (kk + t + 4) * SMS;
            float Af[4][4], Bf[4][2];
#pragma unroll
            for (int mi = 0; mi < 4; mi++) {
                int m0 = arow + mi * 16;
                Af[mi][0] = Ahi[r0 + m0];
                Af[mi][1] = Ahi[r0 + m0 + 8];
                Af[mi][2] = Ahi[r1 + m0];
                Af[mi][3] = Ahi[r1 + m0 + 8];
            }
#pragma unroll
            for (int ni = 0; ni < 4; ni++) {
                int n0 = bcol + ni * 8;
                Bf[ni][0] = Bhi[r0 + n0];
                Bf[ni][1] = Bhi[r1 + n0];
            }
#pragma unroll
            for (int mi = 0; mi < 4; mi++)
#pragma unroll
                for (int ni = 0; ni < 4; ni++)
                    MMA_TF32(acc[mi][ni], Af[mi][0], Af[mi][1], Af[mi][2],
                             Af[mi][3], Bf[ni][0], Bf[ni][1]);

            // pass 2: Alo x Bhi
            float Al[4][4];
#pragma unroll
            for (int mi = 0; mi < 4; mi++) {
                int m0 = arow + mi * 16;
                Al[mi][0] = Alo[r0 + m0];
                Al[mi][1] = Alo[r0 + m0 + 8];
                Al[mi][2] = Alo[r1 + m0];
                Al[mi][3] = Alo[r1 + m0 + 8];
            }
#pragma unroll
            for (int mi = 0; mi < 4; mi++)
#pragma unroll
                for (int ni = 0; ni < 4; ni++)
                    MMA_TF32(acc[mi][ni], Al[mi][0], Al[mi][1], Al[mi][2],
                             Al[mi][3], Bf[ni][0], Bf[ni][1]);

            // pass 3: Ahi x Blo
            float Bl[4][2];
#pragma unroll
            for (int ni = 0; ni < 4; ni++) {
                int n0 = bcol + ni * 8;
                Bl[ni][0] = Blo[r0 + n0];
                Bl[ni][1] = Blo[r1 + n0];
            }
#pragma unroll
            for (int mi = 0; mi < 4; mi++)
#pragma unroll
                for (int ni = 0; ni < 4; ni++)
                    MMA_TF32(acc[mi][ni], Af[mi][0], Af[mi][1], Af[mi][2],
                             Af[mi][3], Bl[ni][0], Bl[ni][1]);
        }
    }

    // epilogue
#pragma unroll
    for (int mi = 0; mi < 4; mi++) {
        int r0 = bm + wm * 64 + mi * 16 + g;
#pragma unroll
        for (int ni = 0; ni < 4; ni++) {
            int col = bn + wn * 32 + ni * 8 + 2 * t;
            float bx = bias[col], by = bias[col + 1];
#pragma unroll
            for (int h = 0; h < 2; h++) {
                int r = r0 + h * 8;
                float vx = acc[mi][ni][2 * h + 0] + bx;
                float vy = acc[mi][ni][2 * h + 1] + by;
                if (act) {
                    vx = 0.5f * vx * (1.f + erff(vx * 0.70710678118654752f));
                    vy = 0.5f * vy * (1.f + erff(vy * 0.70710678118654752f));
                }
                if (res) {
                    const float2 rr = *(const float2*)(res + (size_t)r * Nc + col);
                    vx += rr.x; vy += rr.y;
                }
                float2 o; o.x = vx; o.y = vy;
                *(float2*)(C + (size_t)r * Nc + col) = o;
            }
        }
    }
}

// ---------------------------------------------------------------------------
__global__ void __launch_bounds__(256) topk_kernel(const float* __restrict__ pos,
    const float* __restrict__ cptr, int* __restrict__ idxo, float* __restrict__ disto)
{
    __shared__ float arg[NTOK];
    __shared__ float rv[8];
    __shared__ int ri[8];
    int row = blockIdx.x;
    int b = row >> 11, i = row & (NTOK - 1);
    float c = cptr[0];
    float inv_sqc = rsqrtf(c);
    const float* pb = pos + (size_t)b * NTOK * 2;
    float yx = pb[i * 2], yy = pb[i * 2 + 1];
    float denY = 1.f - c * (yx * yx + yy * yy);
    for (int j = threadIdx.x; j < NTOK; j += 256) {
        float xx = pb[j * 2], xy = pb[j * 2 + 1];
        float dx = xx - yx, dy = xy - yy;
        float num = 2.f * c * (dx * dx + dy * dy);
        float den = (1.f - c * (xx * xx + xy * xy)) * denY;
        arg[j] = fmaxf(1.f + num / (den + 1e-8f), 1.f);
    }
    __syncthreads();
    int lane = threadIdx.x & 31, w = threadIdx.x >> 5;
    for (int sel = 0; sel < KNN; sel++) {
        float bv = 3.4e38f; int bi = 0x7fffffff;
        for (int j = threadIdx.x; j < NTOK; j += 256) {
            float a = arg[j];
            if (a < bv) { bv = a; bi = j; }
        }
#pragma unroll
        for (int o = 16; o; o >>= 1) {
            float ov = __shfl_xor_sync(0xffffffffu, bv, o);
            int   oi = __shfl_xor_sync(0xffffffffu, bi, o);
            if (ov < bv || (ov == bv && oi < bi)) { bv = ov; bi = oi; }
        }
        if (lane == 0) { rv[w] = bv; ri[w] = bi; }
        __syncthreads();
        if (threadIdx.x == 0) {
            float fv = rv[0]; int fi = ri[0];
            for (int t2 = 1; t2 < 8; t2++)
                if (rv[t2] < fv || (rv[t2] == fv && ri[t2] < fi)) { fv = rv[t2]; fi = ri[t2]; }
            idxo[(size_t)row * KNN + sel] = fi;
            disto[(size_t)row * KNN + sel] = acoshf(fv) * inv_sqc;
            arg[fi] = 3.4e38f;
        }
        __syncthreads();
    }
}

// ---------------------------------------------------------------------------
__global__ void __launch_bounds__(384) attn_kernel(const float* __restrict__ q,
    const float* __restrict__ k, const float* __restrict__ v,
    const int* __restrict__ idx, const float* __restrict__ dist,
    const float* __restrict__ log_tau, float* __restrict__ out)
{
    __shared__ int sidx[KNN];
    __shared__ float sgeo[KNN];
    int row = blockIdx.x;
    int lane = threadIdx.x & 31, h = threadIdx.x >> 5;
    float invtau = 1.f / (expf(log_tau[0]) + 1e-8f);
    if (threadIdx.x < KNN) {
        sidx[threadIdx.x] = idx[(size_t)row * KNN + threadIdx.x];
        sgeo[threadIdx.x] = -dist[(size_t)row * KNN + threadIdx.x] * invtau;
    }
    __syncthreads();
    int b = row >> 11;
    const float* qp = q + (size_t)row * DIMV + h * HDIM;
    float q0 = qp[2 * lane], q1 = qp[2 * lane + 1];
    const float* kb = k + (size_t)b * NTOK * DIMV + h * HDIM;
    const float* vb = v + (size_t)b * NTOK * DIMV + h * HDIM;
    float myscore = 0.f;
#pragma unroll 4
    for (int j = 0; j < KNN; j++) {
        const float* kp = kb + (size_t)sidx[j] * DIMV;
        float p = q0 * kp[2 * lane] + q1 * kp[2 * lane + 1];
#pragma unroll
        for (int o = 16; o; o >>= 1) p += __shfl_xor_sync(0xffffffffu, p, o);
        if (lane == j) myscore = p * 0.125f + sgeo[j];
    }
    float m = myscore;
#pragma unroll
    for (int o = 16; o; o >>= 1) m = fmaxf(m, __shfl_xor_sync(0xffffffffu, m, o));
    float e = expf(myscore - m);
    float s = e;
#pragma unroll
    for (int o = 16; o; o >>= 1) s += __shfl_xor_sync(0xffffffffu, s, o);
    float p = e / s;
    float o0 = 0.f, o1 = 0.f;
#pragma unroll 4
    for (int j = 0; j < KNN; j++) {
        float pj = __shfl_sync(0xffffffffu, p, j);
        const float* vp = vb + (size_t)sidx[j] * DIMV;
        o0 += pj * vp[2 * lane]; o1 += pj * vp[2 * lane + 1];
    }
    float* op = out + (size_t)row * DIMV + h * HDIM;
    op[2 * lane] = o0; op[2 * lane + 1] = o1;
}

// ---------------------------------------------------------------------------
extern "C" void kernel_launch(void* const* d_in, const int* in_sizes, int n_in,
                              void* d_out, int out_size)
{
    const float* x    = (const float*)d_in[0];
    const float* pos  = (const float*)d_in[1];
    const float* c    = (const float*)d_in[2];
    const float* temb = (const float*)d_in[3];
    const float* Wq = (const float*)d_in[4],  *bq = (const float*)d_in[5];
    const float* Wk = (const float*)d_in[6],  *bk = (const float*)d_in[7];
    const float* Wv = (const float*)d_in[8],  *bv = (const float*)d_in[9];
    const float* Wo = (const float*)d_in[10], *bo = (const float*)d_in[11];
    const float* W1 = (const float*)d_in[12], *b1 = (const float*)d_in[13];
    const float* W2 = (const float*)d_in[14], *b2 = (const float*)d_in[15];
    const float* g1 = (const float*)d_in[16], *be1 = (const float*)d_in[17];
    const float* g2 = (const float*)d_in[18], *be2 = (const float*)d_in[19];
    const float* log_tau = (const float*)d_in[20];
    float* out = (float*)d_out;

    float* base; cudaGetSymbolAddress((void**)&base, g_scratch);
    int* idxp;   cudaGetSymbolAddress((void**)&idxp, g_idx);
    float* distp;cudaGetSymbolAddress((void**)&distp, g_dist);

    float* h   = base;
    float* q   = base + 1 * (size_t)MROWS * DIMV;
    float* k   = base + 2 * (size_t)MROWS * DIMV;
    float* v   = base + 3 * (size_t)MROWS * DIMV;
    float* att = base + 4 * (size_t)MROWS * DIMV;
    float* x2  = base + 5 * (size_t)MROWS * DIMV;
    float* h2  = base + 6 * (size_t)MROWS * DIMV;
    float* ffn = base + 7 * (size_t)MROWS * DIMV;

    ln_kernel<<<MROWS, 256>>>(x, g1, be1, temb, h);

    dim3 g768(DIMV / 128, MROWS / 128);
    mma_gemm_kernel<<<g768, 256>>>(h, Wq, bq, nullptr, q, MROWS, DIMV, DIMV, 0);
    mma_gemm_kernel<<<g768, 256>>>(h, Wk, bk, nullptr, k, MROWS, DIMV, DIMV, 0);
    mma_gemm_kernel<<<g768, 256>>>(h, Wv, bv, nullptr, v, MROWS, DIMV, DIMV, 0);

    topk_kernel<<<MROWS, 256>>>(pos, c, idxp, distp);
    attn_kernel<<<MROWS, 384>>>(q, k, v, idxp, distp, log_tau, att);

    mma_gemm_kernel<<<g768, 256>>>(att, Wo, bo, x, x2, MROWS, DIMV, DIMV, 0);
    ln_kernel<<<MROWS, 256>>>(x2, g2, be2, nullptr, h2);

    dim3 gff(DFF / 128, MROWS / 128);
    mma_gemm_kernel<<<gff, 256>>>(h2, W1, b1, nullptr, ffn, MROWS, DFF, DIMV, 1);
    mma_gemm_kernel<<<g768, 256>>>(ffn, W2, b2, x2, out, MROWS, DIMV, DFF, 0);
}

// round 3
// speedup vs baseline: 1.9312x; 1.8384x over previous
#include <cuda_runtime.h>
#include <cuda_bf16.h>
#include <math.h>
#include <stdint.h>

#define NTOK 2048
#define BATCH 2
#define DIMV 768
#define NHEAD 12
#define HDIM 64
#define KNN 32
#define DFF 3072
#define MROWS 4096   // BATCH*NTOK

// ---------------------------------------------------------------------------
// global scratch (uint32 words). Layout carved in kernel_launch.
// total words ~41.8M -> ~167MB
#define W_H    ((size_t)MROWS * 384)        // packed pair-words per activation (768/2)
#define W_QKV  ((size_t)MROWS * DIMV)       // fp32 words
#define W_FFN  ((size_t)MROWS * 1536)       // packed ffn (3072/2)
#define W_W768 ((size_t)384 * 768)          // packed weight 768x768
#define W_W1   ((size_t)384 * 3072)
#define W_W2   ((size_t)1536 * 768)
#define TOTAL_WORDS (2*W_H /*h*/ + 3*W_QKV /*qkv*/ + 2*W_H /*att*/ + W_QKV /*x2*/ \
                     + 2*W_H /*h2*/ + 2*W_FFN + 8*W_W768 + 2*W_W1 + 2*W_W2)
__device__ uint32_t g_buf[TOTAL_WORDS];
__device__ int   g_idx[MROWS * KNN];
__device__ float g_dist[MROWS * KNN];

// ---------------------------------------------------------------------------
// bf16 hi/lo pair packing: word = (bf16(odd)<<16) | bf16(even)
__device__ __forceinline__ void pack_pair(float x, float y, uint32_t& whi, uint32_t& wlo) {
    __nv_bfloat16 hx = __float2bfloat16_rn(x);
    __nv_bfloat16 hy = __float2bfloat16_rn(y);
    float rx = x - __bfloat162float(hx);
    float ry = y - __bfloat162float(hy);
    __nv_bfloat16 lx = __float2bfloat16_rn(rx);
    __nv_bfloat16 ly = __float2bfloat16_rn(ry);
    whi = (uint32_t)__bfloat16_as_ushort(hx) | ((uint32_t)__bfloat16_as_ushort(hy) << 16);
    wlo = (uint32_t)__bfloat16_as_ushort(lx) | ((uint32_t)__bfloat16_as_ushort(ly) << 16);
}

// ---------------------------------------------------------------------------
// weight convert: W[K][Nc] fp32 -> packed [KP][Nc] (pair along K)
__global__ void __launch_bounds__(256) wconv_kernel(const float* __restrict__ W,
    uint32_t* __restrict__ hi, uint32_t* __restrict__ lo, int KP, int Nc)
{
    size_t i = (size_t)blockIdx.x * 256 + threadIdx.x;
    if (i >= (size_t)KP * Nc) return;
    int kp = (int)(i / Nc), n = (int)(i % Nc);
    float e = W[(size_t)(2 * kp) * Nc + n];
    float o = W[(size_t)(2 * kp + 1) * Nc + n];
    pack_pair(e, o, hi[i], lo[i]);
}

// ---------------------------------------------------------------------------
// LayerNorm (+time emb) -> packed bf16 hi/lo output. 384 threads, 2 elems each.
__global__ void __launch_bounds__(384) ln_pack_kernel(const float* __restrict__ x,
    const float* __restrict__ g, const float* __restrict__ be,
    const float* __restrict__ temb, uint32_t* __restrict__ ohi, uint32_t* __restrict__ olo)
{
    __shared__ float sb[13];
    int row = blockIdx.x, tid = threadIdx.x;
    int lane = tid & 31, w = tid >> 5;
    float2 xv = *(const float2*)(x + (size_t)row * DIMV + 2 * tid);
    float s = xv.x + xv.y;
#pragma unroll
    for (int o = 16; o; o >>= 1) s += __shfl_xor_sync(0xffffffffu, s, o);
    if (lane == 0) sb[w] = s;
    __syncthreads();
    if (w == 0) {
        float r = (lane < 12) ? sb[lane] : 0.f;
#pragma unroll
        for (int o = 16; o; o >>= 1) r += __shfl_xor_sync(0xffffffffu, r, o);
        if (lane == 0) sb[12] = r;
    }
    __syncthreads();
    float mu = sb[12] * (1.0f / DIMV);
    float dx = xv.x - mu, dy = xv.y - mu;
    float vs = dx * dx + dy * dy;
    __syncthreads();
#pragma unroll
    for (int o = 16; o; o >>= 1) vs += __shfl_xor_sync(0xffffffffu, vs, o);
    if (lane == 0) sb[w] = vs;
    __syncthreads();
    if (w == 0) {
        float r = (lane < 12) ? sb[lane] : 0.f;
#pragma unroll
        for (int o = 16; o; o >>= 1) r += __shfl_xor_sync(0xffffffffu, r, o);
        if (lane == 0) sb[12] = r;
    }
    __syncthreads();
    float inv = rsqrtf(sb[12] * (1.0f / DIMV) + 1e-5f);
    int b = row >> 11;
    int i0 = 2 * tid;
    float o0 = dx * inv * g[i0] + be[i0];
    float o1 = dy * inv * g[i0 + 1] + be[i0 + 1];
    if (temb) { o0 += temb[b * DIMV + i0]; o1 += temb[b * DIMV + i0 + 1]; }
    uint32_t wh, wl;
    pack_pair(o0, o1, wh, wl);
    ohi[(size_t)row * 384 + tid] = wh;
    olo[(size_t)row * 384 + tid] = wl;
}

// ---------------------------------------------------------------------------
// bf16 tensor-core GEMM, 3-pass hi/lo compensation.
// A packed [M][KP], B packed [KP][Nc]. 128x128x32 tile, cp.async 3 stages.
// ---------------------------------------------------------------------------
#define AW 20                 // A smem row stride (words), 16 used
#define BW 136                // B smem row stride (words), 128 used
#define A_WORDS (128 * AW)    // 2560
#define B_WORDS (16 * BW)     // 2176
#define STAGE_W (2 * A_WORDS + 2 * B_WORDS)   // 9472 words
#define SMEM_BYTES (3 * STAGE_W * 4)          // 113664

__device__ __forceinline__ void cp16(uint32_t* dst, const uint32_t* src) {
    unsigned d = (unsigned)__cvta_generic_to_shared(dst);
    asm volatile("cp.async.cg.shared.global [%0], [%1], 16;" :: "r"(d), "l"(src));
}

#define MMA_BF16(d, a, b)                                                     \
    asm volatile(                                                             \
        "mma.sync.aligned.m16n8k16.row.col.f32.bf16.bf16.f32 "                \
        "{%0,%1,%2,%3},{%4,%5,%6,%7},{%8,%9},{%0,%1,%2,%3};"                  \
        : "+f"(d[0]), "+f"(d[1]), "+f"(d[2]), "+f"(d[3])                      \
        : "r"(a[0]), "r"(a[1]), "r"(a[2]), "r"(a[3]), "r"(b[0]), "r"(b[1]))

__global__ void __launch_bounds__(256, 1) mma_gemm_kernel(
    const uint32_t* __restrict__ Ahi, const uint32_t* __restrict__ Alo,
    const uint32_t* __restrict__ Bhi, const uint32_t* __restrict__ Blo,
    const float* __restrict__ bias, const float* __restrict__ res,
    float* __restrict__ Cf, uint32_t* __restrict__ Chi, uint32_t* __restrict__ Clo,
    int M, int Nc, int K, int act)
{
    extern __shared__ uint32_t sm[];
    const int tid = threadIdx.x;
    const int warp = tid >> 5, lane = tid & 31;
    const int g = lane >> 2, t = lane & 3;
    const int wm = warp & 1, wn = warp >> 1;
    const int bm = blockIdx.y * 128, bn = blockIdx.x * 128;
    const int KP = K >> 1;
    const int nk = K >> 5;     // BK=32 -> 16 pairs per iter

    // staging ids
    const int am0 = tid >> 2,  acq = (tid & 3) * 4;       // +64 rows for rep1
    const int bp0 = tid >> 5,  bcn = (tid & 31) * 4;      // +8 prows for rep1

    float acc[4][4][4];
#pragma unroll
    for (int mi = 0; mi < 4; mi++)
#pragma unroll
        for (int ni = 0; ni < 4; ni++)
#pragma unroll
            for (int e = 0; e < 4; e++) acc[mi][ni][e] = 0.f;

    // ---- load stage: slot buffer buf, k-iter it
    auto load_stage = [&](int buf, int it) {
        if (it < nk) {
            uint32_t* st = sm + buf * STAGE_W;
            int kp0 = it * 16;
#pragma unroll
            for (int rep = 0; rep < 2; rep++) {
                int m = am0 + rep * 64;
                size_t asrc = (size_t)(bm + m) * KP + kp0 + acq;
                cp16(st + m * AW + acq, Ahi + asrc);
                cp16(st + A_WORDS + m * AW + acq, Alo + asrc);
                int p = bp0 + rep * 8;
                size_t bsrc = (size_t)(kp0 + p) * Nc + bn + bcn;
                cp16(st + 2 * A_WORDS + p * BW + bcn, Bhi + bsrc);
                cp16(st + 2 * A_WORDS + B_WORDS + p * BW + bcn, Blo + bsrc);
            }
        }
        asm volatile("cp.async.commit_group;");
    };

    load_stage(0, 0);
    load_stage(1, 1);

    const int arow = wm * 64 + g;
    const int bcol = wn * 32 + g;

    for (int it = 0; it < nk; it++) {
        asm volatile("cp.async.wait_group 1;");
        __syncthreads();
        load_stage((it + 2) % 3, it + 2);

        uint32_t* st = sm + (it % 3) * STAGE_W;
        const uint32_t* As_hi = st;
        const uint32_t* As_lo = st + A_WORDS;
        const uint32_t* Bs_hi = st + 2 * A_WORDS;
        const uint32_t* Bs_lo = st + 2 * A_WORDS + B_WORDS;

#pragma unroll
        for (int kk = 0; kk < 2; kk++) {
            const int pb = kk * 8 + t;
            uint32_t Ah[4][4], Bh[4][2];
#pragma unroll
            for (int mi = 0; mi < 4; mi++) {
                int m0 = arow + mi * 16;
                Ah[mi][0] = As_hi[m0 * AW + pb];
                Ah[mi][1] = As_hi[(m0 + 8) * AW + pb];
                Ah[mi][2] = As_hi[m0 * AW + pb + 4];
                Ah[mi][3] = As_hi[(m0 + 8) * AW + pb + 4];
            }
#pragma unroll
            for (int ni = 0; ni < 4; ni++) {
                int n0 = bcol + ni * 8;
                Bh[ni][0] = Bs_hi[pb * BW + n0];
                Bh[ni][1] = Bs_hi[(pb + 4) * BW + n0];
            }
#pragma unroll
            for (int mi = 0; mi < 4; mi++)
#pragma unroll
                for (int ni = 0; ni < 4; ni++)
                    MMA_BF16(acc[mi][ni], Ah[mi], Bh[ni]);

            uint32_t Al[4][4];
#pragma unroll
            for (int mi = 0; mi < 4; mi++) {
                int m0 = arow + mi * 16;
                Al[mi][0] = As_lo[m0 * AW + pb];
                Al[mi][1] = As_lo[(m0 + 8) * AW + pb];
                Al[mi][2] = As_lo[m0 * AW + pb + 4];
                Al[mi][3] = As_lo[(m0 + 8) * AW + pb + 4];
            }
#pragma unroll
            for (int mi = 0; mi < 4; mi++)
#pragma unroll
                for (int ni = 0; ni < 4; ni++)
                    MMA_BF16(acc[mi][ni], Al[mi], Bh[ni]);

            uint32_t Bl[4][2];
#pragma unroll
            for (int ni = 0; ni < 4; ni++) {
                int n0 = bcol + ni * 8;
                Bl[ni][0] = Bs_lo[pb * BW + n0];
                Bl[ni][1] = Bs_lo[(pb + 4) * BW + n0];
            }
#pragma unroll
            for (int mi = 0; mi < 4; mi++)
#pragma unroll
                for (int ni = 0; ni < 4; ni++)
                    MMA_BF16(acc[mi][ni], Ah[mi], Bl[ni]);
        }
    }

    // epilogue
#pragma unroll
    for (int mi = 0; mi < 4; mi++) {
        int r0 = bm + wm * 64 + mi * 16 + g;
#pragma unroll
        for (int ni = 0; ni < 4; ni++) {
            int col = bn + wn * 32 + ni * 8 + 2 * t;
            float2 bb = *(const float2*)(bias + col);
#pragma unroll
            for (int h = 0; h < 2; h++) {
                int r = r0 + h * 8;
                float vx = acc[mi][ni][2 * h + 0] + bb.x;
                float vy = acc[mi][ni][2 * h + 1] + bb.y;
                if (act) {
                    vx = 0.5f * vx * (1.f + erff(vx * 0.70710678118654752f));
                    vy = 0.5f * vy * (1.f + erff(vy * 0.70710678118654752f));
                }
                if (Cf) {
                    if (res) {
                        const float2 rr = *(const float2*)(res + (size_t)r * Nc + col);
                        vx += rr.x; vy += rr.y;
                    }
                    float2 o; o.x = vx; o.y = vy;
                    *(float2*)(Cf + (size_t)r * Nc + col) = o;
                } else {
                    uint32_t wh, wl;
                    pack_pair(vx, vy, wh, wl);
                    size_t ci = (size_t)r * (Nc >> 1) + (col >> 1);
                    Chi[ci] = wh; Clo[ci] = wl;
                }
            }
        }
    }
}

// ---------------------------------------------------------------------------
// Poincare distance + top-KNN per row.
// ---------------------------------------------------------------------------
__global__ void __launch_bounds__(256) topk_kernel(const float* __restrict__ pos,
    const float* __restrict__ cptr, int* __restrict__ idxo, float* __restrict__ disto)
{
    __shared__ float arg[NTOK];
    __shared__ float rv[8];
    __shared__ int ri[8];
    int row = blockIdx.x;
    int b = row >> 11, i = row & (NTOK - 1);
    float c = cptr[0];
    float inv_sqc = rsqrtf(c);
    const float* pb = pos + (size_t)b * NTOK * 2;
    float yx = pb[i * 2], yy = pb[i * 2 + 1];
    float denY = 1.f - c * (yx * yx + yy * yy);
    for (int j = threadIdx.x; j < NTOK; j += 256) {
        float xx = pb[j * 2], xy = pb[j * 2 + 1];
        float dx = xx - yx, dy = xy - yy;
        float num = 2.f * c * (dx * dx + dy * dy);
        float den = (1.f - c * (xx * xx + xy * xy)) * denY;
        arg[j] = fmaxf(1.f + num / (den + 1e-8f), 1.f);
    }
    __syncthreads();
    int lane = threadIdx.x & 31, w = threadIdx.x >> 5;
    for (int sel = 0; sel < KNN; sel++) {
        float bv = 3.4e38f; int bi = 0x7fffffff;
        for (int j = threadIdx.x; j < NTOK; j += 256) {
            float a = arg[j];
            if (a < bv) { bv = a; bi = j; }
        }
#pragma unroll
        for (int o = 16; o; o >>= 1) {
            float ov = __shfl_xor_sync(0xffffffffu, bv, o);
            int   oi = __shfl_xor_sync(0xffffffffu, bi, o);
            if (ov < bv || (ov == bv && oi < bi)) { bv = ov; bi = oi; }
        }
        if (lane == 0) { rv[w] = bv; ri[w] = bi; }
        __syncthreads();
        if (threadIdx.x == 0) {
            float fv = rv[0]; int fi = ri[0];
            for (int t2 = 1; t2 < 8; t2++)
                if (rv[t2] < fv || (rv[t2] == fv && ri[t2] < fi)) { fv = rv[t2]; fi = ri[t2]; }
            idxo[(size_t)row * KNN + sel] = fi;
            disto[(size_t)row * KNN + sel] = acoshf(fv) * inv_sqc;
            arg[fi] = 3.4e38f;
        }
        __syncthreads();
    }
}

// ---------------------------------------------------------------------------
// kNN attention. One block per (b,n); warp=head; packed bf16 hi/lo output.
// ---------------------------------------------------------------------------
__global__ void __launch_bounds__(384) attn_kernel(const float* __restrict__ q,
    const float* __restrict__ k, const float* __restrict__ v,
    const int* __restrict__ idx, const float* __restrict__ dist,
    const float* __restrict__ log_tau,
    uint32_t* __restrict__ ohi, uint32_t* __restrict__ olo)
{
    __shared__ int sidx[KNN];
    __shared__ float sgeo[KNN];
    int row = blockIdx.x;
    int lane = threadIdx.x & 31, h = threadIdx.x >> 5;
    float invtau = 1.f / (expf(log_tau[0]) + 1e-8f);
    if (threadIdx.x < KNN) {
        sidx[threadIdx.x] = idx[(size_t)row * KNN + threadIdx.x];
        sgeo[threadIdx.x] = -dist[(size_t)row * KNN + threadIdx.x] * invtau;
    }
    __syncthreads();
    int b = row >> 11;
    const float* qp = q + (size_t)row * DIMV + h * HDIM;
    float q0 = qp[2 * lane], q1 = qp[2 * lane + 1];
    const float* kb = k + (size_t)b * NTOK * DIMV + h * HDIM;
    const float* vb = v + (size_t)b * NTOK * DIMV + h * HDIM;
    float myscore = 0.f;
#pragma unroll 4
    for (int j = 0; j < KNN; j++) {
        const float* kp = kb + (size_t)sidx[j] * DIMV;
        float p = q0 * kp[2 * lane] + q1 * kp[2 * lane + 1];
#pragma unroll
        for (int o = 16; o; o >>= 1) p += __shfl_xor_sync(0xffffffffu, p, o);
        if (lane == j) myscore = p * 0.125f + sgeo[j];
    }
    float m = myscore;
#pragma unroll
    for (int o = 16; o; o >>= 1) m = fmaxf(m, __shfl_xor_sync(0xffffffffu, m, o));
    float e = expf(myscore - m);
    float s = e;
#pragma unroll
    for (int o = 16; o; o >>= 1) s += __shfl_xor_sync(0xffffffffu, s, o);
    float p = e / s;
    float o0 = 0.f, o1 = 0.f;
#pragma unroll 4
    for (int j = 0; j < KNN; j++) {
        float pj = __shfl_sync(0xffffffffu, p, j);
        const float* vp = vb + (size_t)sidx[j] * DIMV;
        o0 += pj * vp[2 * lane]; o1 += pj * vp[2 * lane + 1];
    }
    uint32_t wh, wl;
    pack_pair(o0, o1, wh, wl);
    size_t wi = (size_t)row * 384 + h * 32 + lane;
    ohi[wi] = wh; olo[wi] = wl;
}

// ---------------------------------------------------------------------------
extern "C" void kernel_launch(void* const* d_in, const int* in_sizes, int n_in,
                              void* d_out, int out_size)
{
    const float* x    = (const float*)d_in[0];
    const float* pos  = (const float*)d_in[1];
    const float* c    = (const float*)d_in[2];
    const float* temb = (const float*)d_in[3];
    const float* Wq = (const float*)d_in[4],  *bq = (const float*)d_in[5];
    const float* Wk = (const float*)d_in[6],  *bk = (const float*)d_in[7];
    const float* Wv = (const float*)d_in[8],  *bv = (const float*)d_in[9];
    const float* Wo = (const float*)d_in[10], *bo = (const float*)d_in[11];
    const float* W1 = (const float*)d_in[12], *b1 = (const float*)d_in[13];
    const float* W2 = (const float*)d_in[14], *b2 = (const float*)d_in[15];
    const float* g1 = (const float*)d_in[16], *be1 = (const float*)d_in[17];
    const float* g2 = (const float*)d_in[18], *be2 = (const float*)d_in[19];
    const float* log_tau = (const float*)d_in[20];
    float* out = (float*)d_out;

    uint32_t* base; cudaGetSymbolAddress((void**)&base, g_buf);
    int* idxp;      cudaGetSymbolAddress((void**)&idxp, g_idx);
    float* distp;   cudaGetSymbolAddress((void**)&distp, g_dist);

    uint32_t* p = base;
    uint32_t *hHi = p; p += W_H;  uint32_t *hLo = p; p += W_H;
    float *q = (float*)p; p += W_QKV;
    float *k = (float*)p; p += W_QKV;
    float *v = (float*)p; p += W_QKV;
    uint32_t *attHi = p; p += W_H; uint32_t *attLo = p; p += W_H;
    float *x2 = (float*)p; p += W_QKV;
    uint32_t *h2Hi = p; p += W_H; uint32_t *h2Lo = p; p += W_H;
    uint32_t *ffnHi = p; p += W_FFN; uint32_t *ffnLo = p; p += W_FFN;
    uint32_t *WqHi = p; p += W_W768; uint32_t *WqLo = p; p += W_W768;
    uint32_t *WkHi = p; p += W_W768; uint32_t *WkLo = p; p += W_W768;
    uint32_t *WvHi = p; p += W_W768; uint32_t *WvLo = p; p += W_W768;
    uint32_t *WoHi = p; p += W_W768; uint32_t *WoLo = p; p += W_W768;
    uint32_t *W1Hi = p; p += W_W1;   uint32_t *W1Lo = p; p += W_W1;
    uint32_t *W2Hi = p; p += W_W2;   uint32_t *W2Lo = p; p += W_W2;

    cudaFuncSetAttribute(mma_gemm_kernel,
                         cudaFuncAttributeMaxDynamicSharedMemorySize, SMEM_BYTES);

    // weight conversions
    wconv_kernel<<<(int)((W_W768 + 255) / 256), 256>>>(Wq, WqHi, WqLo, 384, 768);
    wconv_kernel<<<(int)((W_W768 + 255) / 256), 256>>>(Wk, WkHi, WkLo, 384, 768);
    wconv_kernel<<<(int)((W_W768 + 255) / 256), 256>>>(Wv, WvHi, WvLo, 384, 768);
    wconv_kernel<<<(int)((W_W768 + 255) / 256), 256>>>(Wo, WoHi, WoLo, 384, 768);
    wconv_kernel<<<(int)((W_W1 + 255) / 256), 256>>>(W1, W1Hi, W1Lo, 384, 3072);
    wconv_kernel<<<(int)((W_W2 + 255) / 256), 256>>>(W2, W2Hi, W2Lo, 1536, 768);

    ln_pack_kernel<<<MROWS, 384>>>(x, g1, be1, temb, hHi, hLo);

    dim3 g768(DIMV / 128, MROWS / 128);
    mma_gemm_kernel<<<g768, 256, SMEM_BYTES>>>(hHi, hLo, WqHi, WqLo, bq, nullptr,
                                               q, nullptr, nullptr, MROWS, DIMV, DIMV, 0);
    mma_gemm_kernel<<<g768, 256, SMEM_BYTES>>>(hHi, hLo, WkHi, WkLo, bk, nullptr,
                                               k, nullptr, nullptr, MROWS, DIMV, DIMV, 0);
    mma_gemm_kernel<<<g768, 256, SMEM_BYTES>>>(hHi, hLo, WvHi, WvLo, bv, nullptr,
                                               v, nullptr, nullptr, MROWS, DIMV, DIMV, 0);

    topk_kernel<<<MROWS, 256>>>(pos, c, idxp, distp);
    attn_kernel<<<MROWS, 384>>>(q, k, v, idxp, distp, log_tau, attHi, attLo);

    mma_gemm_kernel<<<g768, 256, SMEM_BYTES>>>(attHi, attLo, WoHi, WoLo, bo, x,
                                               x2, nullptr, nullptr, MROWS, DIMV, DIMV, 0);
    ln_pack_kernel<<<MROWS, 384>>>(x2, g2, be2, nullptr, h2Hi, h2Lo);

    dim3 gff(DFF / 128, MROWS / 128);
    mma_gemm_kernel<<<gff, 256, SMEM_BYTES>>>(h2Hi, h2Lo, W1Hi, W1Lo, b1, nullptr,
                                              nullptr, ffnHi, ffnLo, MROWS, DFF, DIMV, 1);
    mma_gemm_kernel<<<g768, 256, SMEM_BYTES>>>(ffnHi, ffnLo, W2Hi, W2Lo, b2, x2,
                                               out, nullptr, nullptr, MROWS, DIMV, DFF, 0);
}

// round 5
// speedup vs baseline: 2.4209x; 1.2536x over previous
#include <cuda_runtime.h>
#include <cuda_bf16.h>
#include <math.h>
#include <stdint.h>

#define NTOK 2048
#define BATCH 2
#define DIMV 768
#define NHEAD 12
#define HDIM 64
#define KNN 32
#define DFF 3072
#define MROWS 4096   // BATCH*NTOK

// ---------------------------------------------------------------------------
// scratch (uint32 words)
#define W_HH   ((size_t)MROWS * 384)        // packed activation (768/2)
#define W_QKV  ((size_t)MROWS * 2304)       // fused qkv fp32
#define W_X2   ((size_t)MROWS * 768)
#define W_FFN  ((size_t)MROWS * 1536)       // packed ffn (3072/2)
#define W_WQKV ((size_t)2304 * 384)
#define W_WO   ((size_t)768 * 384)
#define W_W1T  ((size_t)3072 * 384)
#define W_W2T  ((size_t)768 * 1536)
#define TOTAL_WORDS (2*W_HH + W_QKV + 2*W_HH + W_X2 + 2*W_HH + 2*W_FFN \
                     + 2*W_WQKV + 2*W_WO + 2*W_W1T + 2*W_W2T + 2304)
__device__ uint32_t g_buf[TOTAL_WORDS];
__device__ int   g_idx[MROWS * KNN];
__device__ float g_dist[MROWS * KNN];

// ---------------------------------------------------------------------------
__device__ __forceinline__ void pack_pair(float x, float y, uint32_t& whi, uint32_t& wlo) {
    __nv_bfloat16 hx = __float2bfloat16_rn(x);
    __nv_bfloat16 hy = __float2bfloat16_rn(y);
    float rx = x - __bfloat162float(hx);
    float ry = y - __bfloat162float(hy);
    __nv_bfloat16 lx = __float2bfloat16_rn(rx);
    __nv_bfloat16 ly = __float2bfloat16_rn(ry);
    whi = (uint32_t)__bfloat16_as_ushort(hx) | ((uint32_t)__bfloat16_as_ushort(hy) << 16);
    wlo = (uint32_t)__bfloat16_as_ushort(lx) | ((uint32_t)__bfloat16_as_ushort(ly) << 16);
}

__device__ __forceinline__ float gelu_f(float v) {
    return 0.5f * v * (1.f + erff(v * 0.70710678118654752f));
}

// ---------------------------------------------------------------------------
// transpose-convert: W[K][Nc] fp32 -> hi/lo packed [Nc][KP] (pairs along K)
__global__ void __launch_bounds__(256) wconvT_kernel(const float* __restrict__ W,
    uint32_t* __restrict__ hi, uint32_t* __restrict__ lo,
    int Nc, int outStride, int rowOff)
{
    __shared__ uint32_t shH[32][33], shL[32][33];
    int tx = threadIdx.x & 31;
    int ty = threadIdx.x >> 5;
    int n0 = blockIdx.x * 32, kp0 = blockIdx.y * 32;
#pragma unroll
    for (int j = 0; j < 4; j++) {
        int kpl = ty * 4 + j, kp = kp0 + kpl;
        float e = W[(size_t)(2 * kp) * Nc + n0 + tx];
        float o = W[(size_t)(2 * kp + 1) * Nc + n0 + tx];
        uint32_t wh, wl; pack_pair(e, o, wh, wl);
        shH[kpl][tx] = wh; shL[kpl][tx] = wl;
    }
    __syncthreads();
#pragma unroll
    for (int j = 0; j < 4; j++) {
        int nl = ty * 4 + j;
        size_t oidx = (size_t)(rowOff + n0 + nl) * outStride + kp0 + tx;
        hi[oidx] = shH[tx][nl];
        lo[oidx] = shL[tx][nl];
    }
}

__global__ void bcat_kernel(const float* __restrict__ a, const float* __restrict__ b,
                            const float* __restrict__ c, float* __restrict__ o)
{
    int i = blockIdx.x * 256 + threadIdx.x;
    if (i >= 2304) return;
    o[i] = (i < 768) ? a[i] : (i < 1536 ? b[i - 768] : c[i - 1536]);
}

// ---------------------------------------------------------------------------
// LayerNorm (+time emb) -> packed bf16 hi/lo
__global__ void __launch_bounds__(384) ln_pack_kernel(const float* __restrict__ x,
    const float* __restrict__ g, const float* __restrict__ be,
    const float* __restrict__ temb, uint32_t* __restrict__ ohi, uint32_t* __restrict__ olo)
{
    __shared__ float sb[13];
    int row = blockIdx.x, tid = threadIdx.x;
    int lane = tid & 31, w = tid >> 5;
    float2 xv = *(const float2*)(x + (size_t)row * DIMV + 2 * tid);
    float s = xv.x + xv.y;
#pragma unroll
    for (int o = 16; o; o >>= 1) s += __shfl_xor_sync(0xffffffffu, s, o);
    if (lane == 0) sb[w] = s;
    __syncthreads();
    if (w == 0) {
        float r = (lane < 12) ? sb[lane] : 0.f;
#pragma unroll
        for (int o = 16; o; o >>= 1) r += __shfl_xor_sync(0xffffffffu, r, o);
        if (lane == 0) sb[12] = r;
    }
    __syncthreads();
    float mu = sb[12] * (1.0f / DIMV);
    float dx = xv.x - mu, dy = xv.y - mu;
    float vs = dx * dx + dy * dy;
    __syncthreads();
#pragma unroll
    for (int o = 16; o; o >>= 1) vs += __shfl_xor_sync(0xffffffffu, vs, o);
    if (lane == 0) sb[w] = vs;
    __syncthreads();
    if (w == 0) {
        float r = (lane < 12) ? sb[lane] : 0.f;
#pragma unroll
        for (int o = 16; o; o >>= 1) r += __shfl_xor_sync(0xffffffffu, r, o);
        if (lane == 0) sb[12] = r;
    }
    __syncthreads();
    float inv = rsqrtf(sb[12] * (1.0f / DIMV) + 1e-5f);
    int b = row >> 11;
    int i0 = 2 * tid;
    float o0 = dx * inv * g[i0] + be[i0];
    float o1 = dy * inv * g[i0 + 1] + be[i0 + 1];
    if (temb) { o0 += temb[b * DIMV + i0]; o1 += temb[b * DIMV + i0 + 1]; }
    uint32_t wh, wl;
    pack_pair(o0, o1, wh, wl);
    ohi[(size_t)row * 384 + tid] = wh;
    olo[(size_t)row * 384 + tid] = wl;
}

// ---------------------------------------------------------------------------
// bf16 mma.sync GEMM, 3-pass hi/lo, ldmatrix fragments, 2 CTAs/SM.
// A packed [M][KP], B packed [Nc][KP]. Tile 128x128, BK=32, 2-stage cp.async.
// ---------------------------------------------------------------------------
// per-stage word offsets
#define S_AHI 0
#define S_ALO 2048
#define S_BHI 4096
#define S_BLO 6144
#define STG_WORDS 8192                 // 32KB per stage
#define GEMM_SMEM (2 * STG_WORDS * 4)  // 64KB

__device__ __forceinline__ void cp16s(uint32_t sdst, const uint32_t* src) {
    asm volatile("cp.async.cg.shared.global [%0], [%1], 16;" :: "r"(sdst), "l"(src));
}

#define LDSM4(r, addr)                                                        \
    asm volatile("ldmatrix.sync.aligned.m8n8.x4.shared.b16 {%0,%1,%2,%3}, [%4];" \
        : "=r"((r)[0]), "=r"((r)[1]), "=r"((r)[2]), "=r"((r)[3]) : "r"(addr))

#define MMA16816(d, a, b0, b1)                                                \
    asm volatile(                                                             \
        "mma.sync.aligned.m16n8k16.row.col.f32.bf16.bf16.f32 "                \
        "{%0,%1,%2,%3},{%4,%5,%6,%7},{%8,%9},{%0,%1,%2,%3};"                  \
        : "+f"(d[0]), "+f"(d[1]), "+f"(d[2]), "+f"(d[3])                      \
        : "r"((a)[0]), "r"((a)[1]), "r"((a)[2]), "r"((a)[3]), "r"(b0), "r"(b1))

__global__ void __launch_bounds__(256, 2) tc_gemm_kernel(
    const uint32_t* __restrict__ Ahi, const uint32_t* __restrict__ Alo,
    const uint32_t* __restrict__ Bhi, const uint32_t* __restrict__ Blo,
    const float* __restrict__ bias, const float* __restrict__ res,
    float* __restrict__ Cf, uint32_t* __restrict__ Chi, uint32_t* __restrict__ Clo,
    int Nc, int K, int act)
{
    extern __shared__ __align__(128) uint32_t smw[];
    const int tid = threadIdx.x;
    const int warp = tid >> 5, lane = tid & 31;
    const int wm = warp & 1, wn = warp >> 1;          // warp tile 64x32
    const int g = lane >> 2, t = lane & 3;
    const int bm = blockIdx.y * 128, bn = blockIdx.x * 128;
    const int KP = K >> 1;
    const int nk = K >> 5;                            // BK=32 -> 16 words

    uint32_t sbase;
    asm("{ .reg .u64 tt; cvta.to.shared.u64 tt, %1; cvt.u32.u64 %0, tt; }"
        : "=r"(sbase) : "l"(smw));

    // ---- per-lane ldmatrix byte offsets (within a sub-buffer)
    // A: lanes 0-15 rows m0..m0+15 (klo chunk), 16-31 same rows (khi chunk)
    const int arl = lane & 15, aqb = lane >> 4;
    const int arsw = (arl >> 1) & 3;
    uint32_t aoff[4], aq[2];
#pragma unroll
    for (int mi = 0; mi < 4; mi++)
        aoff[mi] = (uint32_t)(wm * 64 + mi * 16 + arl) * 64u;
#pragma unroll
    for (int kk = 0; kk < 2; kk++)
        aq[kk] = (uint32_t)(((2 * kk + aqb) ^ arsw) << 4);
    // B: lanes 0-7 n0-7 klo, 8-15 n0-7 khi, 16-23 n8-15 klo, 24-31 n8-15 khi
    const int nrl = (lane & 7) + ((lane >> 4) << 3);
    const int bqb = (lane >> 3) & 1;
    const int brsw = (nrl >> 1) & 3;
    uint32_t boff[2], bq[2];
#pragma unroll
    for (int nh = 0; nh < 2; nh++)
        boff[nh] = (uint32_t)(wn * 32 + nh * 16 + nrl) * 64u;
#pragma unroll
    for (int kk = 0; kk < 2; kk++)
        bq[kk] = (uint32_t)(((2 * kk + bqb) ^ brsw) << 4);

    float acc[4][4][4];
#pragma unroll
    for (int mi = 0; mi < 4; mi++)
#pragma unroll
        for (int ni = 0; ni < 4; ni++)
#pragma unroll
            for (int e = 0; e < 4; e++) acc[mi][ni][e] = 0.f;

    // ---- stage loader: 8 cp.async x 16B per thread
    auto load_stage = [&](int buf, int it) {
        if (it < nk) {
            uint32_t st = sbase + buf * (STG_WORDS * 4);
            int kp0 = it * 16;
#pragma unroll
            for (int r2 = 0; r2 < 2; r2++) {
                int idx = tid + r2 * 256;
                int m = idx >> 2, q = idx & 3;
                uint32_t woff = (uint32_t)(m * 64 + ((q ^ ((m >> 1) & 3)) << 4));
                size_t ga = (size_t)(bm + m) * KP + kp0 + q * 4;
                cp16s(st + S_AHI * 4 + woff, Ahi + ga);
                cp16s(st + S_ALO * 4 + woff, Alo + ga);
                size_t gb = (size_t)(bn + m) * KP + kp0 + q * 4;
                cp16s(st + S_BHI * 4 + woff, Bhi + gb);
                cp16s(st + S_BLO * 4 + woff, Blo + gb);
            }
        }
        asm volatile("cp.async.commit_group;");
    };

    load_stage(0, 0);
    load_stage(1, 1);

    for (int it = 0; it < nk; it++) {
        asm volatile("cp.async.wait_group 1;");
        __syncthreads();
        uint32_t st = sbase + (it & 1) * (STG_WORDS * 4);

#pragma unroll
        for (int kk = 0; kk < 2; kk++) {
            uint32_t Ah[4][4], Al[4][4], Bb[2][4];
#pragma unroll
            for (int mi = 0; mi < 4; mi++)
                LDSM4(Ah[mi], st + S_AHI * 4 + aoff[mi] + aq[kk]);
#pragma unroll
            for (int nh = 0; nh < 2; nh++)
                LDSM4(Bb[nh], st + S_BHI * 4 + boff[nh] + bq[kk]);
            // pass 1: Ahi x Bhi
#pragma unroll
            for (int mi = 0; mi < 4; mi++)
#pragma unroll
                for (int ni = 0; ni < 4; ni++)
                    MMA16816(acc[mi][ni], Ah[mi], Bb[ni >> 1][(ni & 1) * 2],
                             Bb[ni >> 1][(ni & 1) * 2 + 1]);
            // pass 2: Alo x Bhi
#pragma unroll
            for (int mi = 0; mi < 4; mi++)
                LDSM4(Al[mi], st + S_ALO * 4 + aoff[mi] + aq[kk]);
#pragma unroll
            for (int mi = 0; mi < 4; mi++)
#pragma unroll
                for (int ni = 0; ni < 4; ni++)
                    MMA16816(acc[mi][ni], Al[mi], Bb[ni >> 1][(ni & 1) * 2],
                             Bb[ni >> 1][(ni & 1) * 2 + 1]);
            // pass 3: Ahi x Blo
#pragma unroll
            for (int nh = 0; nh < 2; nh++)
                LDSM4(Bb[nh], st + S_BLO * 4 + boff[nh] + bq[kk]);
#pragma unroll
            for (int mi = 0; mi < 4; mi++)
#pragma unroll
                for (int ni = 0; ni < 4; ni++)
                    MMA16816(acc[mi][ni], Ah[mi], Bb[ni >> 1][(ni & 1) * 2],
                             Bb[ni >> 1][(ni & 1) * 2 + 1]);
        }
        __syncthreads();
        load_stage(it & 1, it + 2);
    }

    // ---- epilogue straight from accumulators
#pragma unroll
    for (int mi = 0; mi < 4; mi++) {
        int r0 = bm + wm * 64 + mi * 16 + g;
#pragma unroll
        for (int ni = 0; ni < 4; ni++) {
            int col = bn + wn * 32 + ni * 8 + 2 * t;
            float bx = bias[col], by = bias[col + 1];
#pragma unroll
            for (int hh = 0; hh < 2; hh++) {
                int r = r0 + hh * 8;
                float vx = acc[mi][ni][2 * hh + 0] + bx;
                float vy = acc[mi][ni][2 * hh + 1] + by;
                if (act) { vx = gelu_f(vx); vy = gelu_f(vy); }
                if (Cf) {
                    if (res) {
                        const float2 rr = *(const float2*)(res + (size_t)r * Nc + col);
                        vx += rr.x; vy += rr.y;
                    }
                    float2 o; o.x = vx; o.y = vy;
                    *(float2*)(Cf + (size_t)r * Nc + col) = o;
                } else {
                    uint32_t wh, wl;
                    pack_pair(vx, vy, wh, wl);
                    size_t ci = (size_t)r * (Nc >> 1) + (col >> 1);
                    Chi[ci] = wh; Clo[ci] = wl;
                }
            }
        }
    }
}

// ---------------------------------------------------------------------------
// Poincare distance + top-KNN per row
__global__ void __launch_bounds__(256) topk_kernel(const float* __restrict__ pos,
    const float* __restrict__ cptr, int* __restrict__ idxo, float* __restrict__ disto)
{
    __shared__ float arg[NTOK];
    __shared__ float rv[8];
    __shared__ int ri[8];
    int row = blockIdx.x;
    int b = row >> 11, i = row & (NTOK - 1);
    float c = cptr[0];
    float inv_sqc = rsqrtf(c);
    const float* pb = pos + (size_t)b * NTOK * 2;
    float yx = pb[i * 2], yy = pb[i * 2 + 1];
    float denY = 1.f - c * (yx * yx + yy * yy);
    for (int j = threadIdx.x; j < NTOK; j += 256) {
        float xx = pb[j * 2], xy = pb[j * 2 + 1];
        float dx = xx - yx, dy = xy - yy;
        float num = 2.f * c * (dx * dx + dy * dy);
        float den = (1.f - c * (xx * xx + xy * xy)) * denY;
        arg[j] = fmaxf(1.f + num / (den + 1e-8f), 1.f);
    }
    __syncthreads();
    int lane = threadIdx.x & 31, w = threadIdx.x >> 5;
    for (int sel = 0; sel < KNN; sel++) {
        float bv = 3.4e38f; int bi = 0x7fffffff;
        for (int j = threadIdx.x; j < NTOK; j += 256) {
            float a = arg[j];
            if (a < bv) { bv = a; bi = j; }
        }
#pragma unroll
        for (int o = 16; o; o >>= 1) {
            float ov = __shfl_xor_sync(0xffffffffu, bv, o);
            int   oi = __shfl_xor_sync(0xffffffffu, bi, o);
            if (ov < bv || (ov == bv && oi < bi)) { bv = ov; bi = oi; }
        }
        if (lane == 0) { rv[w] = bv; ri[w] = bi; }
        __syncthreads();
        if (threadIdx.x == 0) {
            float fv = rv[0]; int fi = ri[0];
            for (int t2 = 1; t2 < 8; t2++)
                if (rv[t2] < fv || (rv[t2] == fv && ri[t2] < fi)) { fv = rv[t2]; fi = ri[t2]; }
            idxo[(size_t)row * KNN + sel] = fi;
            disto[(size_t)row * KNN + sel] = acoshf(fv) * inv_sqc;
            arg[fi] = 3.4e38f;
        }
        __syncthreads();
    }
}

// ---------------------------------------------------------------------------
// kNN attention over fused qkv [row][2304]; packed output
__global__ void __launch_bounds__(384) attn_kernel(const float* __restrict__ qkv,
    const int* __restrict__ idx, const float* __restrict__ dist,
    const float* __restrict__ log_tau,
    uint32_t* __restrict__ ohi, uint32_t* __restrict__ olo)
{
    __shared__ int sidx[KNN];
    __shared__ float sgeo[KNN];
    int row = blockIdx.x;
    int lane = threadIdx.x & 31, h = threadIdx.x >> 5;
    float invtau = 1.f / (expf(log_tau[0]) + 1e-8f);
    if (threadIdx.x < KNN) {
        sidx[threadIdx.x] = idx[(size_t)row * KNN + threadIdx.x];
        sgeo[threadIdx.x] = -dist[(size_t)row * KNN + threadIdx.x] * invtau;
    }
    __syncthreads();
    int b = row >> 11;
    const float* qp = qkv + (size_t)row * 2304 + h * HDIM;
    float q0 = qp[2 * lane], q1 = qp[2 * lane + 1];
    const float* kb = qkv + (size_t)b * NTOK * 2304 + 768 + h * HDIM;
    const float* vb = qkv + (size_t)b * NTOK * 2304 + 1536 + h * HDIM;
    float myscore = 0.f;
#pragma unroll 4
    for (int j = 0; j < KNN; j++) {
        const float* kp = kb + (size_t)sidx[j] * 2304;
        float p = q0 * kp[2 * lane] + q1 * kp[2 * lane + 1];
#pragma unroll
        for (int o = 16; o; o >>= 1) p += __shfl_xor_sync(0xffffffffu, p, o);
        if (lane == j) myscore = p * 0.125f + sgeo[j];
    }
    float m = myscore;
#pragma unroll
    for (int o = 16; o; o >>= 1) m = fmaxf(m, __shfl_xor_sync(0xffffffffu, m, o));
    float e = expf(myscore - m);
    float s = e;
#pragma unroll
    for (int o = 16; o; o >>= 1) s += __shfl_xor_sync(0xffffffffu, s, o);
    float p = e / s;
    float o0 = 0.f, o1 = 0.f;
#pragma unroll 4
    for (int j = 0; j < KNN; j++) {
        float pj = __shfl_sync(0xffffffffu, p, j);
        const float* vp = vb + (size_t)sidx[j] * 2304;
        o0 += pj * vp[2 * lane]; o1 += pj * vp[2 * lane + 1];
    }
    uint32_t wh, wl;
    pack_pair(o0, o1, wh, wl);
    size_t wi = (size_t)row * 384 + h * 32 + lane;
    ohi[wi] = wh; olo[wi] = wl;
}

// ---------------------------------------------------------------------------
extern "C" void kernel_launch(void* const* d_in, const int* in_sizes, int n_in,
                              void* d_out, int out_size)
{
    const float* x    = (const float*)d_in[0];
    const float* pos  = (const float*)d_in[1];
    const float* c    = (const float*)d_in[2];
    const float* temb = (const float*)d_in[3];
    const float* Wq = (const float*)d_in[4],  *bq = (const float*)d_in[5];
    const float* Wk = (const float*)d_in[6],  *bk = (const float*)d_in[7];
    const float* Wv = (const float*)d_in[8],  *bv = (const float*)d_in[9];
    const float* Wo = (const float*)d_in[10], *bo = (const float*)d_in[11];
    const float* W1 = (const float*)d_in[12], *b1 = (const float*)d_in[13];
    const float* W2 = (const float*)d_in[14], *b2 = (const float*)d_in[15];
    const float* g1 = (const float*)d_in[16], *be1 = (const float*)d_in[17];
    const float* g2 = (const float*)d_in[18], *be2 = (const float*)d_in[19];
    const float* log_tau = (const float*)d_in[20];
    float* out = (float*)d_out;

    uint32_t* base; cudaGetSymbolAddress((void**)&base, g_buf);
    int* idxp;      cudaGetSymbolAddress((void**)&idxp, g_idx);
    float* distp;   cudaGetSymbolAddress((void**)&distp, g_dist);

    uint32_t* p = base;
    uint32_t *hHi = p; p += W_HH;  uint32_t *hLo = p; p += W_HH;
    float *qkv = (float*)p; p += W_QKV;
    uint32_t *attHi = p; p += W_HH; uint32_t *attLo = p; p += W_HH;
    float *x2 = (float*)p; p += W_X2;
    uint32_t *h2Hi = p; p += W_HH; uint32_t *h2Lo = p; p += W_HH;
    uint32_t *ffnHi = p; p += W_FFN; uint32_t *ffnLo = p; p += W_FFN;
    uint32_t *WqkvHi = p; p += W_WQKV; uint32_t *WqkvLo = p; p += W_WQKV;
    uint32_t *WoHi = p; p += W_WO; uint32_t *WoLo = p; p += W_WO;
    uint32_t *W1Hi = p; p += W_W1T; uint32_t *W1Lo = p; p += W_W1T;
    uint32_t *W2Hi = p; p += W_W2T; uint32_t *W2Lo = p; p += W_W2T;
    float *bqkv = (float*)p; p += 2304;

    cudaFuncSetAttribute(tc_gemm_kernel,
                         cudaFuncAttributeMaxDynamicSharedMemorySize, GEMM_SMEM);

    // weight transpose-conversions + bias concat
    wconvT_kernel<<<dim3(24, 12), 256>>>(Wq, WqkvHi, WqkvLo, 768, 384, 0);
    wconvT_kernel<<<dim3(24, 12), 256>>>(Wk, WqkvHi, WqkvLo, 768, 384, 768);
    wconvT_kernel<<<dim3(24, 12), 256>>>(Wv, WqkvHi, WqkvLo, 768, 384, 1536);
    wconvT_kernel<<<dim3(24, 12), 256>>>(Wo, WoHi, WoLo, 768, 384, 0);
    wconvT_kernel<<<dim3(96, 12), 256>>>(W1, W1Hi, W1Lo, 3072, 384, 0);
    wconvT_kernel<<<dim3(24, 48), 256>>>(W2, W2Hi, W2Lo, 768, 1536, 0);
    bcat_kernel<<<9, 256>>>(bq, bk, bv, bqkv);

    ln_pack_kernel<<<MROWS, 384>>>(x, g1, be1, temb, hHi, hLo);

    // fused QKV: [4096,768] @ [768,2304]
    tc_gemm_kernel<<<dim3(18, 32), 256, GEMM_SMEM>>>(hHi, hLo, WqkvHi, WqkvLo,
        bqkv, nullptr, qkv, nullptr, nullptr, 2304, 768, 0);

    topk_kernel<<<MROWS, 256>>>(pos, c, idxp, distp);
    attn_kernel<<<MROWS, 384>>>(qkv, idxp, distp, log_tau, attHi, attLo);

    // x2 = x + att @ Wo
    tc_gemm_kernel<<<dim3(6, 32), 256, GEMM_SMEM>>>(attHi, attLo, WoHi, WoLo,
        bo, x, x2, nullptr, nullptr, 768, 768, 0);
    ln_pack_kernel<<<MROWS, 384>>>(x2, g2, be2, nullptr, h2Hi, h2Lo);

    // ffn = gelu(h2 @ W1)  (packed out)
    tc_gemm_kernel<<<dim3(24, 32), 256, GEMM_SMEM>>>(h2Hi, h2Lo, W1Hi, W1Lo,
        b1, nullptr, nullptr, ffnHi, ffnLo, 3072, 768, 1);
    // out = x2 + ffn @ W2
    tc_gemm_kernel<<<dim3(6, 32), 256, GEMM_SMEM>>>(ffnHi, ffnLo, W2Hi, W2Lo,
        b2, x2, out, nullptr, nullptr, 768, 3072, 0);
}